// round 5
// baseline (speedup 1.0000x reference)
#include <cuda_runtime.h>
#include <math.h>
#include <float.h>

#define BB 32
#define NN 1000
#define CC 105
#define MAXC 512
#define POOLMAX 24576
#define DETS 100

// ---- scratch (device globals: no allocation allowed) ----
__device__ int    g_cand_cnt[BB * CC];
__device__ float  g_cand_score[BB * CC * MAXC];
__device__ float4 g_cand_box[BB * CC * MAXC];
__device__ int    g_cand_n[BB * CC * MAXC];

__device__ int    g_pool_cnt[BB];
__device__ float  g_pool_score[BB * POOLMAX];
__device__ float4 g_pool_box[BB * POOLMAX];
__device__ int    g_pool_lab[BB * POOLMAX];

__global__ void reset_kernel() {
    int t = blockIdx.x * blockDim.x + threadIdx.x;
    if (t < BB * CC) g_cand_cnt[t] = 0;
    if (t < BB)      g_pool_cnt[t] = 0;
}

// One block per (b, n) proposal. 128 threads cover C=105 classes.
// Softmax -> threshold -> decode only valid (prob > 0.05) pairs -> scatter.
__global__ void score_decode_kernel(const float* __restrict__ logits,
                                    const float* __restrict__ reg,
                                    const float* __restrict__ props) {
    const int pn  = blockIdx.x;              // 0 .. BB*NN-1
    const int tid = threadIdx.x;
    const float* L = logits + (size_t)pn * CC;

    __shared__ float red[128];

    float v = (tid < CC) ? L[tid] : -INFINITY;
    red[tid] = v;
    __syncthreads();
    for (int s = 64; s > 0; s >>= 1) {
        if (tid < s) red[tid] = fmaxf(red[tid], red[tid + s]);
        __syncthreads();
    }
    float m = red[0];
    __syncthreads();

    float e = (tid < CC) ? expf(v - m) : 0.0f;
    red[tid] = e;
    __syncthreads();
    for (int s = 64; s > 0; s >>= 1) {
        if (tid < s) red[tid] += red[tid + s];
        __syncthreads();
    }
    float S = red[0];

    if (tid >= 1 && tid < CC) {
        float p = e / S;
        if (p > 0.05f) {
            const int b = pn / NN;
            const int n = pn - b * NN;
            // decode box for class `tid`
            const float* P = props + (size_t)pn * 4;
            float px1 = P[0], py1 = P[1], px2 = P[2], py2 = P[3];
            float w  = px2 - px1 + 1.0f;
            float h  = py2 - py1 + 1.0f;
            float cx = px1 + 0.5f * w;
            float cy = py1 + 0.5f * h;
            const float* R = reg + (size_t)pn * (4 * CC) + 4 * tid;
            float dx = R[0] / 10.0f;
            float dy = R[1] / 10.0f;
            const float CLIP = 4.135166556742356f;  // log(1000/16)
            float dw = fminf(R[2] / 5.0f, CLIP);
            float dh = fminf(R[3] / 5.0f, CLIP);
            float pcx = dx * w + cx;
            float pcy = dy * h + cy;
            float pw  = expf(dw) * w;
            float ph  = expf(dh) * h;
            float x1 = fminf(fmaxf(pcx - 0.5f * pw, 0.0f), 1332.0f);
            float y1 = fminf(fmaxf(pcy - 0.5f * ph, 0.0f), 799.0f);
            float x2 = fminf(fmaxf(pcx + 0.5f * pw - 1.0f, 0.0f), 1332.0f);
            float y2 = fminf(fmaxf(pcy + 0.5f * ph - 1.0f, 0.0f), 799.0f);

            int cls = b * CC + tid;
            int pos = atomicAdd(&g_cand_cnt[cls], 1);
            if (pos < MAXC) {
                size_t o = (size_t)cls * MAXC + pos;
                g_cand_score[o] = p;
                g_cand_box[o]   = make_float4(x1, y1, x2, y2);
                g_cand_n[o]     = n;
            }
        }
    }
}

// One block per (b, class j in 1..C-1). Rank-sort candidates desc by score
// (stable by proposal index), greedy NMS, append survivors to image pool.
__global__ void nms_kernel() {
    const int blk = blockIdx.x;
    const int b   = blk / (CC - 1);
    const int j   = 1 + blk % (CC - 1);
    const int cls = b * CC + j;
    const int tid = threadIdx.x;

    int K = g_cand_cnt[cls];
    if (K > MAXC) K = MAXC;
    if (K == 0) return;

    __shared__ float  rs[MAXC];
    __shared__ float4 rb[MAXC];
    __shared__ int    rn[MAXC];
    __shared__ float  ss[MAXC];
    __shared__ float4 sb[MAXC];
    __shared__ int    supp[MAXC];

    for (int i = tid; i < K; i += blockDim.x) {
        size_t o = (size_t)cls * MAXC + i;
        rs[i] = g_cand_score[o];
        rb[i] = g_cand_box[o];
        rn[i] = g_cand_n[o];
    }
    __syncthreads();

    // rank = number of elements strictly ahead in (score desc, n asc) order
    for (int i = tid; i < K; i += blockDim.x) {
        float si = rs[i];
        int   ni = rn[i];
        int rank = 0;
        for (int k = 0; k < K; k++) {
            float sk = rs[k];
            rank += (sk > si) || (sk == si && rn[k] < ni);
        }
        ss[rank]   = si;
        sb[rank]   = rb[i];
        supp[rank] = 0;
    }
    __syncthreads();

    // greedy NMS over sorted order
    for (int i = 0; i < K - 1; i++) {
        if (!supp[i]) {
            float4 bi = sb[i];
            float areaA = (bi.z - bi.x + 1.0f) * (bi.w - bi.y + 1.0f);
            for (int k = i + 1 + tid; k < K; k += blockDim.x) {
                float4 bk = sb[k];
                float lx = fmaxf(bi.x, bk.x);
                float ly = fmaxf(bi.y, bk.y);
                float rx = fminf(bi.z, bk.z);
                float ry = fminf(bi.w, bk.w);
                float iw = fmaxf(rx - lx + 1.0f, 0.0f);
                float ih = fmaxf(ry - ly + 1.0f, 0.0f);
                float inter = iw * ih;
                float areaB = (bk.z - bk.x + 1.0f) * (bk.w - bk.y + 1.0f);
                float iou = inter / (areaA + areaB - inter);
                if (iou > 0.5f) supp[k] = 1;
            }
        }
        __syncthreads();
    }

    for (int i = tid; i < K; i += blockDim.x) {
        if (!supp[i]) {
            int pos = atomicAdd(&g_pool_cnt[b], 1);
            if (pos < POOLMAX) {
                size_t o = (size_t)b * POOLMAX + pos;
                g_pool_score[o] = ss[i];
                g_pool_box[o]   = sb[i];
                g_pool_lab[o]   = j;
            }
        }
    }
}

// One block per image: 100 rounds of destructive argmax over the pool.
// Output layout (float32): det [B,100,5] | labels [B,100] | valid [B,100]
__global__ void topk_kernel(float* __restrict__ out) {
    const int b   = blockIdx.x;
    const int tid = threadIdx.x;
    int M = g_pool_cnt[b];
    if (M > POOLMAX) M = POOLMAX;

    __shared__ float wval[8];
    __shared__ int   widx[8];

    const int nwarps = blockDim.x >> 5;

    for (int r = 0; r < DETS; r++) {
        float best = -INFINITY;
        int   bi   = -1;
        for (int i = tid; i < M; i += blockDim.x) {
            float s = g_pool_score[(size_t)b * POOLMAX + i];
            if (s > best) { best = s; bi = i; }
        }
        // warp reduce (scores are distinct; idx tie-break only for safety)
        for (int o = 16; o > 0; o >>= 1) {
            float ov = __shfl_down_sync(0xffffffffu, best, o);
            int   oi = __shfl_down_sync(0xffffffffu, bi, o);
            if (ov > best || (ov == best && oi != -1 && (bi == -1 || oi < bi))) {
                best = ov; bi = oi;
            }
        }
        if ((tid & 31) == 0) { wval[tid >> 5] = best; widx[tid >> 5] = bi; }
        __syncthreads();
        if (tid == 0) {
            for (int w = 1; w < nwarps; w++) {
                if (wval[w] > best ||
                    (wval[w] == best && widx[w] != -1 && (bi == -1 || widx[w] < bi))) {
                    best = wval[w]; bi = widx[w];
                }
            }
            float* det = out + (size_t)b * (DETS * 5) + r * 5;
            if (r < M && bi >= 0) {
                size_t o = (size_t)b * POOLMAX + bi;
                float4 bx = g_pool_box[o];
                det[0] = bx.x; det[1] = bx.y; det[2] = bx.z; det[3] = bx.w;
                det[4] = best;
                out[BB * DETS * 5 + b * DETS + r]            = (float)g_pool_lab[o];
                out[BB * DETS * 5 + BB * DETS + b * DETS + r] = 1.0f;
                g_pool_score[o] = -INFINITY;   // consume
            } else {
                det[0] = det[1] = det[2] = det[3] = det[4] = 0.0f;
                out[BB * DETS * 5 + b * DETS + r]             = 1.0f;
                out[BB * DETS * 5 + BB * DETS + b * DETS + r] = 0.0f;
            }
        }
        __syncthreads();
    }
}

extern "C" void kernel_launch(void* const* d_in, const int* in_sizes, int n_in,
                              void* d_out, int out_size) {
    // Identify inputs by element count (robust to ordering).
    const float* logits = nullptr;  // 32*1000*105   = 3,360,000
    const float* reg    = nullptr;  // 32*1000*420   = 13,440,000
    const float* props  = nullptr;  // 32*1000*4     = 128,000
    for (int i = 0; i < n_in; i++) {
        if (in_sizes[i] == BB * NN * CC)       logits = (const float*)d_in[i];
        else if (in_sizes[i] == BB * NN * 4 * CC) reg  = (const float*)d_in[i];
        else if (in_sizes[i] == BB * NN * 4)   props  = (const float*)d_in[i];
    }
    float* out = (float*)d_out;

    reset_kernel<<<(BB * CC + 255) / 256, 256>>>();
    score_decode_kernel<<<BB * NN, 128>>>(logits, reg, props);
    nms_kernel<<<BB * (CC - 1), 256>>>();
    topk_kernel<<<BB, 256>>>(out);
}

// round 7
// speedup vs baseline: 2.0732x; 2.0732x over previous
#include <cuda_runtime.h>
#include <math.h>
#include <float.h>

#define BB 32
#define NN 1000
#define CC 105
#define MAXC 512
#define POOLMAX 24576
#define DETS 100

#define HBINS 1536
#define KEYBASE 0x7A00   /* (bits>>15) of floats with exponent 122 (0.03125..0.0625) */
#define CCAP 1024

// ---- scratch (device globals: no allocation allowed) ----
__device__ int    g_cand_cnt[BB * CC];
__device__ float  g_cand_score[BB * CC * MAXC];
__device__ float4 g_cand_box[BB * CC * MAXC];
__device__ int    g_cand_n[BB * CC * MAXC];

__device__ int    g_pool_cnt[BB];
__device__ float  g_pool_score[BB * POOLMAX];
__device__ float4 g_pool_box[BB * POOLMAX];
__device__ int    g_pool_lab[BB * POOLMAX];

__global__ void reset_kernel() {
    int t = blockIdx.x * blockDim.x + threadIdx.x;
    if (t < BB * CC) g_cand_cnt[t] = 0;
    if (t < BB)      g_pool_cnt[t] = 0;
}

// One block per (b, n) proposal. 128 threads cover C=105 classes.
// Softmax -> threshold -> decode only valid (prob > 0.05) pairs -> scatter.
__global__ void score_decode_kernel(const float* __restrict__ logits,
                                    const float* __restrict__ reg,
                                    const float* __restrict__ props) {
    const int pn  = blockIdx.x;              // 0 .. BB*NN-1
    const int tid = threadIdx.x;
    const float* L = logits + (size_t)pn * CC;

    __shared__ float red[128];

    float v = (tid < CC) ? L[tid] : -INFINITY;
    red[tid] = v;
    __syncthreads();
    for (int s = 64; s > 0; s >>= 1) {
        if (tid < s) red[tid] = fmaxf(red[tid], red[tid + s]);
        __syncthreads();
    }
    float m = red[0];
    __syncthreads();

    float e = (tid < CC) ? expf(v - m) : 0.0f;
    red[tid] = e;
    __syncthreads();
    for (int s = 64; s > 0; s >>= 1) {
        if (tid < s) red[tid] += red[tid + s];
        __syncthreads();
    }
    float S = red[0];

    if (tid >= 1 && tid < CC) {
        float p = e / S;
        if (p > 0.05f) {
            const int b = pn / NN;
            const int n = pn - b * NN;
            // decode box for class `tid`
            const float* P = props + (size_t)pn * 4;
            float px1 = P[0], py1 = P[1], px2 = P[2], py2 = P[3];
            float w  = px2 - px1 + 1.0f;
            float h  = py2 - py1 + 1.0f;
            float cx = px1 + 0.5f * w;
            float cy = py1 + 0.5f * h;
            const float* R = reg + (size_t)pn * (4 * CC) + 4 * tid;
            float dx = R[0] / 10.0f;
            float dy = R[1] / 10.0f;
            const float CLIP = 4.135166556742356f;  // log(1000/16)
            float dw = fminf(R[2] / 5.0f, CLIP);
            float dh = fminf(R[3] / 5.0f, CLIP);
            float pcx = dx * w + cx;
            float pcy = dy * h + cy;
            float pw  = expf(dw) * w;
            float ph  = expf(dh) * h;
            float x1 = fminf(fmaxf(pcx - 0.5f * pw, 0.0f), 1332.0f);
            float y1 = fminf(fmaxf(pcy - 0.5f * ph, 0.0f), 799.0f);
            float x2 = fminf(fmaxf(pcx + 0.5f * pw - 1.0f, 0.0f), 1332.0f);
            float y2 = fminf(fmaxf(pcy + 0.5f * ph - 1.0f, 0.0f), 799.0f);

            int cls = b * CC + tid;
            int pos = atomicAdd(&g_cand_cnt[cls], 1);
            if (pos < MAXC) {
                size_t o = (size_t)cls * MAXC + pos;
                g_cand_score[o] = p;
                g_cand_box[o]   = make_float4(x1, y1, x2, y2);
                g_cand_n[o]     = n;
            }
        }
    }
}

// One block per (b, class j in 1..C-1). Rank-sort candidates desc by score
// (stable by proposal index), greedy NMS, append survivors to image pool.
__global__ void nms_kernel() {
    const int blk = blockIdx.x;
    const int b   = blk / (CC - 1);
    const int j   = 1 + blk % (CC - 1);
    const int cls = b * CC + j;
    const int tid = threadIdx.x;

    int K = g_cand_cnt[cls];
    if (K > MAXC) K = MAXC;
    if (K == 0) return;

    __shared__ float  rs[MAXC];
    __shared__ float4 rb[MAXC];
    __shared__ int    rn[MAXC];
    __shared__ float  ss[MAXC];
    __shared__ float4 sb[MAXC];
    __shared__ int    supp[MAXC];

    for (int i = tid; i < K; i += blockDim.x) {
        size_t o = (size_t)cls * MAXC + i;
        rs[i] = g_cand_score[o];
        rb[i] = g_cand_box[o];
        rn[i] = g_cand_n[o];
    }
    __syncthreads();

    // rank = number of elements strictly ahead in (score desc, n asc) order
    for (int i = tid; i < K; i += blockDim.x) {
        float si = rs[i];
        int   ni = rn[i];
        int rank = 0;
        for (int k = 0; k < K; k++) {
            float sk = rs[k];
            rank += (sk > si) || (sk == si && rn[k] < ni);
        }
        ss[rank]   = si;
        sb[rank]   = rb[i];
        supp[rank] = 0;
    }
    __syncthreads();

    // greedy NMS over sorted order
    for (int i = 0; i < K - 1; i++) {
        if (!supp[i]) {
            float4 bi = sb[i];
            float areaA = (bi.z - bi.x + 1.0f) * (bi.w - bi.y + 1.0f);
            for (int k = i + 1 + tid; k < K; k += blockDim.x) {
                float4 bk = sb[k];
                float lx = fmaxf(bi.x, bk.x);
                float ly = fmaxf(bi.y, bk.y);
                float rx = fminf(bi.z, bk.z);
                float ry = fminf(bi.w, bk.w);
                float iw = fmaxf(rx - lx + 1.0f, 0.0f);
                float ih = fmaxf(ry - ly + 1.0f, 0.0f);
                float inter = iw * ih;
                float areaB = (bk.z - bk.x + 1.0f) * (bk.w - bk.y + 1.0f);
                float iou = inter / (areaA + areaB - inter);
                if (iou > 0.5f) supp[k] = 1;
            }
        }
        __syncthreads();
    }

    for (int i = tid; i < K; i += blockDim.x) {
        if (!supp[i]) {
            int pos = atomicAdd(&g_pool_cnt[b], 1);
            if (pos < POOLMAX) {
                size_t o = (size_t)b * POOLMAX + pos;
                g_pool_score[o] = ss[i];
                g_pool_box[o]   = sb[i];
                g_pool_lab[o]   = j;
            }
        }
    }
}

// One block per image: radix-select top-100 via monotone float-bit keys.
// Scores are probabilities in (0.05, 1] -> (bits>>15) is a monotone key in
// [KEYBASE, KEYBASE+1281). Histogram -> threshold key -> compact superset ->
// O(C^2) rank-sort of ~100-150 elements -> emit sorted desc.
// Output layout (float32): det [B,100,5] | labels [B,100] | valid [B,100]
__global__ void topk_kernel(float* __restrict__ out) {
    const int b   = blockIdx.x;
    const int tid = threadIdx.x;
    int M = g_pool_cnt[b];
    if (M > POOLMAX) M = POOLMAX;

    __shared__ int   hist[HBINS];
    __shared__ int   sbsum[HBINS / 16];
    __shared__ float cs[CCAP];
    __shared__ int   ci[CCAP];
    __shared__ int   s_ccount;
    __shared__ int   s_kstar;
    __shared__ float osc[DETS];
    __shared__ int   oix[DETS];

    for (int i = tid; i < HBINS; i += blockDim.x) hist[i] = 0;
    if (tid == 0) { s_ccount = 0; s_kstar = 0; }
    __syncthreads();

    const float* ps = g_pool_score + (size_t)b * POOLMAX;

    // pass 1: histogram of monotone keys
    for (int i = tid; i < M; i += blockDim.x) {
        int key = (int)(__float_as_uint(ps[i]) >> 15) - KEYBASE;
        key = max(0, min(HBINS - 1, key));
        atomicAdd(&hist[key], 1);
    }
    __syncthreads();

    // superbin sums (96 superbins of 16)
    if (tid < HBINS / 16) {
        int s = 0;
        #pragma unroll
        for (int j = 0; j < 16; j++) s += hist[tid * 16 + j];
        sbsum[tid] = s;
    }
    __syncthreads();

    // find threshold key: smallest k* with count(key >= k*) >= min(100, M)
    if (tid == 0) {
        int target = (M < DETS) ? M : DETS;
        int ks = 0;
        if (target > 0) {
            int cum = 0;
            for (int sb2 = HBINS / 16 - 1; sb2 >= 0; sb2--) {
                if (cum + sbsum[sb2] >= target) {
                    for (int bn = sb2 * 16 + 15; bn >= sb2 * 16; bn--) {
                        cum += hist[bn];
                        if (cum >= target) { ks = bn; break; }
                    }
                    break;
                }
                cum += sbsum[sb2];
            }
        }
        s_kstar = ks;
    }
    __syncthreads();
    const int ks = s_kstar;

    // pass 2: compact superset (all elements with key >= k*)
    for (int i = tid; i < M; i += blockDim.x) {
        float s = ps[i];
        int key = (int)(__float_as_uint(s) >> 15) - KEYBASE;
        key = max(0, min(HBINS - 1, key));
        if (key >= ks) {
            int pos = atomicAdd(&s_ccount, 1);
            if (pos < CCAP) { cs[pos] = s; ci[pos] = i; }
        }
    }
    __syncthreads();
    int C = s_ccount;
    if (C > CCAP) C = CCAP;

    // rank-sort the superset; ranks < DETS are the global top-100 (sorted desc)
    for (int e = tid; e < C; e += blockDim.x) {
        float se = cs[e];
        int   ie = ci[e];
        int rank = 0;
        for (int k2 = 0; k2 < C; k2++) {
            float sk = cs[k2];
            rank += (sk > se) || (sk == se && ci[k2] < ie);
        }
        if (rank < DETS) { osc[rank] = se; oix[rank] = ie; }
    }
    __syncthreads();

    const int Mo = (C < DETS) ? C : DETS;
    for (int r = tid; r < DETS; r += blockDim.x) {
        float* det = out + (size_t)b * (DETS * 5) + r * 5;
        if (r < Mo) {
            size_t o = (size_t)b * POOLMAX + oix[r];
            float4 bx = g_pool_box[o];
            det[0] = bx.x; det[1] = bx.y; det[2] = bx.z; det[3] = bx.w;
            det[4] = osc[r];
            out[BB * DETS * 5 + b * DETS + r]             = (float)g_pool_lab[o];
            out[BB * DETS * 5 + BB * DETS + b * DETS + r] = 1.0f;
        } else {
            det[0] = det[1] = det[2] = det[3] = det[4] = 0.0f;
            out[BB * DETS * 5 + b * DETS + r]             = 1.0f;
            out[BB * DETS * 5 + BB * DETS + b * DETS + r] = 0.0f;
        }
    }
}

extern "C" void kernel_launch(void* const* d_in, const int* in_sizes, int n_in,
                              void* d_out, int out_size) {
    // Identify inputs by element count (robust to ordering).
    const float* logits = nullptr;  // 32*1000*105   = 3,360,000
    const float* reg    = nullptr;  // 32*1000*420   = 13,440,000
    const float* props  = nullptr;  // 32*1000*4     = 128,000
    for (int i = 0; i < n_in; i++) {
        if (in_sizes[i] == BB * NN * CC)       logits = (const float*)d_in[i];
        else if (in_sizes[i] == BB * NN * 4 * CC) reg  = (const float*)d_in[i];
        else if (in_sizes[i] == BB * NN * 4)   props  = (const float*)d_in[i];
    }
    float* out = (float*)d_out;

    reset_kernel<<<(BB * CC + 255) / 256, 256>>>();
    score_decode_kernel<<<BB * NN, 128>>>(logits, reg, props);
    nms_kernel<<<BB * (CC - 1), 256>>>();
    topk_kernel<<<BB, 256>>>(out);
}

// round 9
// speedup vs baseline: 2.4219x; 1.1682x over previous
#include <cuda_runtime.h>
#include <math.h>
#include <float.h>

#define BB 32
#define NN 1000
#define CC 105
#define MAXC 512
#define POOLMAX 24576
#define DETS 100

#define HBINS 1536
#define KEYBASE 0x7A00   /* (bits>>15) of floats with exponent 122 */
#define CCAP 1024

// ---- scratch (device globals: zero-initialized at module load) ----
__device__ int    g_cand_cnt[BB * CC];
__device__ float  g_cand_score[BB * CC * MAXC];
__device__ float4 g_cand_box[BB * CC * MAXC];
__device__ int    g_cand_n[BB * CC * MAXC];

__device__ int    g_pool_cnt[BB];
__device__ float  g_pool_score[BB * POOLMAX];
__device__ float4 g_pool_box[BB * POOLMAX];
__device__ int    g_pool_lab[BB * POOLMAX];

__device__ __forceinline__ void decode_and_push(
    int b, int n, int cls_j, float p,
    float w, float h, float cx, float cy,
    const float* __restrict__ reg, int pn)
{
    const float4 rv = *(const float4*)(reg + (size_t)pn * (4 * CC) + 4 * cls_j);
    float dx = rv.x / 10.0f;
    float dy = rv.y / 10.0f;
    const float CLIP = 4.135166556742356f;  // log(1000/16)
    float dw = fminf(rv.z / 5.0f, CLIP);
    float dh = fminf(rv.w / 5.0f, CLIP);
    float pcx = dx * w + cx;
    float pcy = dy * h + cy;
    float pw  = expf(dw) * w;
    float ph  = expf(dh) * h;
    float x1 = fminf(fmaxf(pcx - 0.5f * pw, 0.0f), 1332.0f);
    float y1 = fminf(fmaxf(pcy - 0.5f * ph, 0.0f), 799.0f);
    float x2 = fminf(fmaxf(pcx + 0.5f * pw - 1.0f, 0.0f), 1332.0f);
    float y2 = fminf(fmaxf(pcy + 0.5f * ph - 1.0f, 0.0f), 799.0f);

    int cls = b * CC + cls_j;
    int pos = atomicAdd(&g_cand_cnt[cls], 1);
    if (pos < MAXC) {
        size_t o = (size_t)cls * MAXC + pos;
        g_cand_score[o] = p;
        g_cand_box[o]   = make_float4(x1, y1, x2, y2);
        g_cand_n[o]     = n;
    }
}

// One WARP per proposal. Lane l covers classes {l, l+32, l+64, l+96(<105)}.
// Shuffle-based softmax; threshold; lazy decode. No block barriers.
__global__ void score_decode_kernel(const float* __restrict__ logits,
                                    const float* __restrict__ reg,
                                    const float* __restrict__ props) {
    const int warp = threadIdx.x >> 5;
    const int lane = threadIdx.x & 31;
    const int pn   = blockIdx.x * 8 + warp;   // grid = BB*NN/8
    const float* L = logits + (size_t)pn * CC;

    float v0 = L[lane];
    float v1 = L[lane + 32];
    float v2 = L[lane + 64];
    float v3 = (lane < CC - 96) ? L[lane + 96] : -INFINITY;

    float m = fmaxf(fmaxf(v0, v1), fmaxf(v2, v3));
    #pragma unroll
    for (int o = 16; o > 0; o >>= 1)
        m = fmaxf(m, __shfl_xor_sync(0xffffffffu, m, o));

    float e0 = expf(v0 - m);
    float e1 = expf(v1 - m);
    float e2 = expf(v2 - m);
    float e3 = (lane < CC - 96) ? expf(v3 - m) : 0.0f;
    float S = e0 + e1 + e2 + e3;
    #pragma unroll
    for (int o = 16; o > 0; o >>= 1)
        S += __shfl_xor_sync(0xffffffffu, S, o);

    float p0 = e0 / S, p1 = e1 / S, p2 = e2 / S, p3 = e3 / S;
    bool any = (p0 > 0.05f && lane >= 1) || (p1 > 0.05f) || (p2 > 0.05f) ||
               (p3 > 0.05f && lane < CC - 96);
    if (__ballot_sync(0xffffffffu, any) == 0u) return;

    const int b = pn / NN;
    const int n = pn - b * NN;
    const float4 P = *(const float4*)(props + (size_t)pn * 4);
    float w  = P.z - P.x + 1.0f;
    float h  = P.w - P.y + 1.0f;
    float cx = P.x + 0.5f * w;
    float cy = P.y + 0.5f * h;

    if (lane >= 1 && p0 > 0.05f)      decode_and_push(b, n, lane,      p0, w, h, cx, cy, reg, pn);
    if (p1 > 0.05f)                   decode_and_push(b, n, lane + 32, p1, w, h, cx, cy, reg, pn);
    if (p2 > 0.05f)                   decode_and_push(b, n, lane + 64, p2, w, h, cx, cy, reg, pn);
    if (lane < CC - 96 && p3 > 0.05f) decode_and_push(b, n, lane + 96, p3, w, h, cx, cy, reg, pn);
}

// One block per (b, class j in 1..C-1). Rank-sort candidates desc by score
// (stable by proposal index), greedy NMS, append survivors to image pool.
__global__ void nms_kernel() {
    const int blk = blockIdx.x;
    const int b   = blk / (CC - 1);
    const int j   = 1 + blk % (CC - 1);
    const int cls = b * CC + j;
    const int tid = threadIdx.x;

    int K = g_cand_cnt[cls];
    if (K > MAXC) K = MAXC;
    if (K == 0) return;

    __shared__ float  rs[MAXC];
    __shared__ float4 rb[MAXC];
    __shared__ int    rn[MAXC];
    __shared__ float  ss[MAXC];
    __shared__ float4 sb[MAXC];
    __shared__ int    supp[MAXC];

    for (int i = tid; i < K; i += blockDim.x) {
        size_t o = (size_t)cls * MAXC + i;
        rs[i] = g_cand_score[o];
        rb[i] = g_cand_box[o];
        rn[i] = g_cand_n[o];
    }
    __syncthreads();

    // rank = number of elements strictly ahead in (score desc, n asc) order
    for (int i = tid; i < K; i += blockDim.x) {
        float si = rs[i];
        int   ni = rn[i];
        int rank = 0;
        for (int k = 0; k < K; k++) {
            float sk = rs[k];
            rank += (sk > si) || (sk == si && rn[k] < ni);
        }
        ss[rank]   = si;
        sb[rank]   = rb[i];
        supp[rank] = 0;
    }
    __syncthreads();

    // greedy NMS over sorted order
    for (int i = 0; i < K - 1; i++) {
        if (!supp[i]) {
            float4 bi = sb[i];
            float areaA = (bi.z - bi.x + 1.0f) * (bi.w - bi.y + 1.0f);
            for (int k = i + 1 + tid; k < K; k += blockDim.x) {
                float4 bk = sb[k];
                float lx = fmaxf(bi.x, bk.x);
                float ly = fmaxf(bi.y, bk.y);
                float rx = fminf(bi.z, bk.z);
                float ry = fminf(bi.w, bk.w);
                float iw = fmaxf(rx - lx + 1.0f, 0.0f);
                float ih = fmaxf(ry - ly + 1.0f, 0.0f);
                float inter = iw * ih;
                float areaB = (bk.z - bk.x + 1.0f) * (bk.w - bk.y + 1.0f);
                float iou = inter / (areaA + areaB - inter);
                if (iou > 0.5f) supp[k] = 1;
            }
        }
        __syncthreads();
    }

    for (int i = tid; i < K; i += blockDim.x) {
        if (!supp[i]) {
            int pos = atomicAdd(&g_pool_cnt[b], 1);
            if (pos < POOLMAX) {
                size_t o = (size_t)b * POOLMAX + pos;
                g_pool_score[o] = ss[i];
                g_pool_box[o]   = sb[i];
                g_pool_lab[o]   = j;
            }
        }
    }
}

// One block per image: radix-select top-100 via monotone float-bit keys.
// Also re-zeroes this image's counters at the end (replaces reset_kernel;
// device globals are zero-initialized at load, so call #1 is consistent).
__global__ void topk_kernel(float* __restrict__ out) {
    const int b   = blockIdx.x;
    const int tid = threadIdx.x;
    int M = g_pool_cnt[b];
    if (M > POOLMAX) M = POOLMAX;

    __shared__ int   hist[HBINS];
    __shared__ int   sbsum[HBINS / 16];
    __shared__ float cs[CCAP];
    __shared__ int   ci[CCAP];
    __shared__ int   s_ccount;
    __shared__ int   s_kstar;
    __shared__ float osc[DETS];
    __shared__ int   oix[DETS];

    for (int i = tid; i < HBINS; i += blockDim.x) hist[i] = 0;
    if (tid == 0) { s_ccount = 0; s_kstar = 0; }
    __syncthreads();

    const float* ps = g_pool_score + (size_t)b * POOLMAX;

    // pass 1: histogram of monotone keys
    for (int i = tid; i < M; i += blockDim.x) {
        int key = (int)(__float_as_uint(ps[i]) >> 15) - KEYBASE;
        key = max(0, min(HBINS - 1, key));
        atomicAdd(&hist[key], 1);
    }
    __syncthreads();

    // superbin sums (96 superbins of 16)
    if (tid < HBINS / 16) {
        int s = 0;
        #pragma unroll
        for (int j = 0; j < 16; j++) s += hist[tid * 16 + j];
        sbsum[tid] = s;
    }
    __syncthreads();

    // find threshold key: smallest k* with count(key >= k*) >= min(100, M)
    if (tid == 0) {
        int target = (M < DETS) ? M : DETS;
        int ks = 0;
        if (target > 0) {
            int cum = 0;
            for (int sb2 = HBINS / 16 - 1; sb2 >= 0; sb2--) {
                if (cum + sbsum[sb2] >= target) {
                    for (int bn = sb2 * 16 + 15; bn >= sb2 * 16; bn--) {
                        cum += hist[bn];
                        if (cum >= target) { ks = bn; break; }
                    }
                    break;
                }
                cum += sbsum[sb2];
            }
        }
        s_kstar = ks;
    }
    __syncthreads();
    const int ks = s_kstar;

    // pass 2: compact superset (all elements with key >= k*)
    for (int i = tid; i < M; i += blockDim.x) {
        float s = ps[i];
        int key = (int)(__float_as_uint(s) >> 15) - KEYBASE;
        key = max(0, min(HBINS - 1, key));
        if (key >= ks) {
            int pos = atomicAdd(&s_ccount, 1);
            if (pos < CCAP) { cs[pos] = s; ci[pos] = i; }
        }
    }
    __syncthreads();
    int C = s_ccount;
    if (C > CCAP) C = CCAP;

    // rank-sort the superset; ranks < DETS are the global top-100 (sorted desc)
    for (int e = tid; e < C; e += blockDim.x) {
        float se = cs[e];
        int   ie = ci[e];
        int rank = 0;
        for (int k2 = 0; k2 < C; k2++) {
            float sk = cs[k2];
            rank += (sk > se) || (sk == se && ci[k2] < ie);
        }
        if (rank < DETS) { osc[rank] = se; oix[rank] = ie; }
    }
    __syncthreads();

    const int Mo = (C < DETS) ? C : DETS;
    for (int r = tid; r < DETS; r += blockDim.x) {
        float* det = out + (size_t)b * (DETS * 5) + r * 5;
        if (r < Mo) {
            size_t o = (size_t)b * POOLMAX + oix[r];
            float4 bx = g_pool_box[o];
            det[0] = bx.x; det[1] = bx.y; det[2] = bx.z; det[3] = bx.w;
            det[4] = osc[r];
            out[BB * DETS * 5 + b * DETS + r]             = (float)g_pool_lab[o];
            out[BB * DETS * 5 + BB * DETS + b * DETS + r] = 1.0f;
        } else {
            det[0] = det[1] = det[2] = det[3] = det[4] = 0.0f;
            out[BB * DETS * 5 + b * DETS + r]             = 1.0f;
            out[BB * DETS * 5 + BB * DETS + b * DETS + r] = 0.0f;
        }
    }

    // re-zero counters for the next launch (replaces reset_kernel)
    for (int i = tid; i < CC; i += blockDim.x) g_cand_cnt[b * CC + i] = 0;
    if (tid == 0) g_pool_cnt[b] = 0;
}

extern "C" void kernel_launch(void* const* d_in, const int* in_sizes, int n_in,
                              void* d_out, int out_size) {
    const float* logits = nullptr;  // 32*1000*105   = 3,360,000
    const float* reg    = nullptr;  // 32*1000*420   = 13,440,000
    const float* props  = nullptr;  // 32*1000*4     = 128,000
    for (int i = 0; i < n_in; i++) {
        if (in_sizes[i] == BB * NN * CC)       logits = (const float*)d_in[i];
        else if (in_sizes[i] == BB * NN * 4 * CC) reg  = (const float*)d_in[i];
        else if (in_sizes[i] == BB * NN * 4)   props  = (const float*)d_in[i];
    }
    float* out = (float*)d_out;

    score_decode_kernel<<<BB * NN / 8, 256>>>(logits, reg, props);
    nms_kernel<<<BB * (CC - 1), 256>>>();
    topk_kernel<<<BB, 256>>>(out);
}

// round 15
// speedup vs baseline: 2.7616x; 1.1402x over previous
#include <cuda_runtime.h>
#include <math.h>
#include <float.h>

#define BB 32
#define NN 1000
#define CC 105
#define MAXC 512
#define POOLMAX 24576
#define DETS 100

#define HBINS 1536
#define KEYBASE 0x7A00   /* (bits>>15) of floats with exponent 122 */
#define CCAP 1024

// ---- scratch (device globals: zero-initialized at module load) ----
__device__ int    g_cand_cnt[BB * CC];
__device__ float  g_cand_score[BB * CC * MAXC];
__device__ float4 g_cand_box[BB * CC * MAXC];
__device__ int    g_cand_n[BB * CC * MAXC];

__device__ int    g_pool_cnt[BB];
__device__ float  g_pool_score[BB * POOLMAX];
__device__ float4 g_pool_box[BB * POOLMAX];
__device__ int    g_pool_lab[BB * POOLMAX];

__device__ __forceinline__ void decode_and_push(
    int b, int n, int cls_j, float p,
    float w, float h, float cx, float cy,
    const float* __restrict__ reg, int pn)
{
    const float4 rv = *(const float4*)(reg + (size_t)pn * (4 * CC) + 4 * cls_j);
    float dx = rv.x / 10.0f;
    float dy = rv.y / 10.0f;
    const float CLIP = 4.135166556742356f;  // log(1000/16)
    float dw = fminf(rv.z / 5.0f, CLIP);
    float dh = fminf(rv.w / 5.0f, CLIP);
    float pcx = dx * w + cx;
    float pcy = dy * h + cy;
    float pw  = expf(dw) * w;
    float ph  = expf(dh) * h;
    float x1 = fminf(fmaxf(pcx - 0.5f * pw, 0.0f), 1332.0f);
    float y1 = fminf(fmaxf(pcy - 0.5f * ph, 0.0f), 799.0f);
    float x2 = fminf(fmaxf(pcx + 0.5f * pw - 1.0f, 0.0f), 1332.0f);
    float y2 = fminf(fmaxf(pcy + 0.5f * ph - 1.0f, 0.0f), 799.0f);

    int cls = b * CC + cls_j;
    int pos = atomicAdd(&g_cand_cnt[cls], 1);
    if (pos < MAXC) {
        size_t o = (size_t)cls * MAXC + pos;
        g_cand_score[o] = p;
        g_cand_box[o]   = make_float4(x1, y1, x2, y2);
        g_cand_n[o]     = n;
    }
}

// One WARP per proposal. Lane l covers classes {l, l+32, l+64, l+96(<105)}.
// Shuffle-based softmax; threshold; lazy decode. No block barriers.
__global__ void score_decode_kernel(const float* __restrict__ logits,
                                    const float* __restrict__ reg,
                                    const float* __restrict__ props) {
    const int warp = threadIdx.x >> 5;
    const int lane = threadIdx.x & 31;
    const int pn   = blockIdx.x * 8 + warp;   // grid = BB*NN/8
    const float* L = logits + (size_t)pn * CC;

    float v0 = L[lane];
    float v1 = L[lane + 32];
    float v2 = L[lane + 64];
    float v3 = (lane < CC - 96) ? L[lane + 96] : -INFINITY;

    float m = fmaxf(fmaxf(v0, v1), fmaxf(v2, v3));
    #pragma unroll
    for (int o = 16; o > 0; o >>= 1)
        m = fmaxf(m, __shfl_xor_sync(0xffffffffu, m, o));

    float e0 = expf(v0 - m);
    float e1 = expf(v1 - m);
    float e2 = expf(v2 - m);
    float e3 = (lane < CC - 96) ? expf(v3 - m) : 0.0f;
    float S = e0 + e1 + e2 + e3;
    #pragma unroll
    for (int o = 16; o > 0; o >>= 1)
        S += __shfl_xor_sync(0xffffffffu, S, o);

    float p0 = e0 / S, p1 = e1 / S, p2 = e2 / S, p3 = e3 / S;
    bool any = (p0 > 0.05f && lane >= 1) || (p1 > 0.05f) || (p2 > 0.05f) ||
               (p3 > 0.05f && lane < CC - 96);
    if (__ballot_sync(0xffffffffu, any) == 0u) return;

    const int b = pn / NN;
    const int n = pn - b * NN;
    const float4 P = *(const float4*)(props + (size_t)pn * 4);
    float w  = P.z - P.x + 1.0f;
    float h  = P.w - P.y + 1.0f;
    float cx = P.x + 0.5f * w;
    float cy = P.y + 0.5f * h;

    if (lane >= 1 && p0 > 0.05f)      decode_and_push(b, n, lane,      p0, w, h, cx, cy, reg, pn);
    if (p1 > 0.05f)                   decode_and_push(b, n, lane + 32, p1, w, h, cx, cy, reg, pn);
    if (p2 > 0.05f)                   decode_and_push(b, n, lane + 64, p2, w, h, cx, cy, reg, pn);
    if (lane < CC - 96 && p3 > 0.05f) decode_and_push(b, n, lane + 96, p3, w, h, cx, cy, reg, pn);
}

// One block (128 threads) per (b, class j in 1..C-1). Rank-sort candidates
// desc by score (stable by proposal index), greedy NMS, then append survivors
// to the image pool with ONE atomicAdd per block (compact via serial scan).
__global__ void nms_kernel() {
    const int blk = blockIdx.x;
    const int b   = blk / (CC - 1);
    const int j   = 1 + blk % (CC - 1);
    const int cls = b * CC + j;
    const int tid = threadIdx.x;

    int K = g_cand_cnt[cls];
    if (K > MAXC) K = MAXC;
    if (K == 0) return;

    __shared__ float  rs[MAXC];
    __shared__ float4 rb[MAXC];
    __shared__ int    rn[MAXC];   // proposal idx during sort; compact pos after
    __shared__ float  ss[MAXC];
    __shared__ float4 sb[MAXC];
    __shared__ int    supp[MAXC];
    __shared__ int    s_base;

    for (int i = tid; i < K; i += blockDim.x) {
        size_t o = (size_t)cls * MAXC + i;
        rs[i] = g_cand_score[o];
        rb[i] = g_cand_box[o];
        rn[i] = g_cand_n[o];
    }
    __syncthreads();

    // rank = number of elements strictly ahead in (score desc, n asc) order
    for (int i = tid; i < K; i += blockDim.x) {
        float si = rs[i];
        int   ni = rn[i];
        int rank = 0;
        for (int k = 0; k < K; k++) {
            float sk = rs[k];
            rank += (sk > si) || (sk == si && rn[k] < ni);
        }
        ss[rank]   = si;
        sb[rank]   = rb[i];
        supp[rank] = 0;
    }
    __syncthreads();

    // greedy NMS over sorted order
    for (int i = 0; i < K - 1; i++) {
        if (!supp[i]) {
            float4 bi = sb[i];
            float areaA = (bi.z - bi.x + 1.0f) * (bi.w - bi.y + 1.0f);
            for (int k = i + 1 + tid; k < K; k += blockDim.x) {
                float4 bk = sb[k];
                float lx = fmaxf(bi.x, bk.x);
                float ly = fmaxf(bi.y, bk.y);
                float rx = fminf(bi.z, bk.z);
                float ry = fminf(bi.w, bk.w);
                float iw = fmaxf(rx - lx + 1.0f, 0.0f);
                float ih = fmaxf(ry - ly + 1.0f, 0.0f);
                float inter = iw * ih;
                float areaB = (bk.z - bk.x + 1.0f) * (bk.w - bk.y + 1.0f);
                float iou = inter / (areaA + areaB - inter);
                if (iou > 0.5f) supp[k] = 1;
            }
        }
        __syncthreads();
    }

    // compact survivors; ONE pool atomic per block (kills per-address
    // L2-atomic serialization across the ~104 blocks of each image)
    if (tid == 0) {
        int c = 0;
        for (int i = 0; i < K; i++) { rn[i] = c; c += (supp[i] == 0); }
        s_base = atomicAdd(&g_pool_cnt[b], c);
    }
    __syncthreads();

    const int base = s_base;
    for (int i = tid; i < K; i += blockDim.x) {
        if (!supp[i]) {
            int pos = base + rn[i];
            if (pos < POOLMAX) {
                size_t o = (size_t)b * POOLMAX + pos;
                g_pool_score[o] = ss[i];
                g_pool_box[o]   = sb[i];
                g_pool_lab[o]   = j;
            }
        }
    }
}

// One block per image: radix-select top-100 via monotone float-bit keys.
// Also re-zeroes this image's counters at the end (replaces reset_kernel;
// device globals are zero-initialized at load, so call #1 is consistent).
__global__ void topk_kernel(float* __restrict__ out) {
    const int b   = blockIdx.x;
    const int tid = threadIdx.x;
    int M = g_pool_cnt[b];
    if (M > POOLMAX) M = POOLMAX;

    __shared__ int   hist[HBINS];
    __shared__ int   sbsum[HBINS / 16];
    __shared__ float cs[CCAP];
    __shared__ int   ci[CCAP];
    __shared__ int   s_ccount;
    __shared__ int   s_kstar;
    __shared__ float osc[DETS];
    __shared__ int   oix[DETS];

    for (int i = tid; i < HBINS; i += blockDim.x) hist[i] = 0;
    if (tid == 0) { s_ccount = 0; s_kstar = 0; }
    __syncthreads();

    const float* ps = g_pool_score + (size_t)b * POOLMAX;

    // pass 1: histogram of monotone keys
    for (int i = tid; i < M; i += blockDim.x) {
        int key = (int)(__float_as_uint(ps[i]) >> 15) - KEYBASE;
        key = max(0, min(HBINS - 1, key));
        atomicAdd(&hist[key], 1);
    }
    __syncthreads();

    // superbin sums (96 superbins of 16)
    if (tid < HBINS / 16) {
        int s = 0;
        #pragma unroll
        for (int j = 0; j < 16; j++) s += hist[tid * 16 + j];
        sbsum[tid] = s;
    }
    __syncthreads();

    // find threshold key: smallest k* with count(key >= k*) >= min(100, M)
    if (tid == 0) {
        int target = (M < DETS) ? M : DETS;
        int ks = 0;
        if (target > 0) {
            int cum = 0;
            for (int sb2 = HBINS / 16 - 1; sb2 >= 0; sb2--) {
                if (cum + sbsum[sb2] >= target) {
                    for (int bn = sb2 * 16 + 15; bn >= sb2 * 16; bn--) {
                        cum += hist[bn];
                        if (cum >= target) { ks = bn; break; }
                    }
                    break;
                }
                cum += sbsum[sb2];
            }
        }
        s_kstar = ks;
    }
    __syncthreads();
    const int ks = s_kstar;

    // pass 2: compact superset (all elements with key >= k*)
    for (int i = tid; i < M; i += blockDim.x) {
        float s = ps[i];
        int key = (int)(__float_as_uint(s) >> 15) - KEYBASE;
        key = max(0, min(HBINS - 1, key));
        if (key >= ks) {
            int pos = atomicAdd(&s_ccount, 1);
            if (pos < CCAP) { cs[pos] = s; ci[pos] = i; }
        }
    }
    __syncthreads();
    int C = s_ccount;
    if (C > CCAP) C = CCAP;

    // rank-sort the superset; ranks < DETS are the global top-100 (sorted desc)
    for (int e = tid; e < C; e += blockDim.x) {
        float se = cs[e];
        int   ie = ci[e];
        int rank = 0;
        for (int k2 = 0; k2 < C; k2++) {
            float sk = cs[k2];
            rank += (sk > se) || (sk == se && ci[k2] < ie);
        }
        if (rank < DETS) { osc[rank] = se; oix[rank] = ie; }
    }
    __syncthreads();

    const int Mo = (C < DETS) ? C : DETS;
    for (int r = tid; r < DETS; r += blockDim.x) {
        float* det = out + (size_t)b * (DETS * 5) + r * 5;
        if (r < Mo) {
            size_t o = (size_t)b * POOLMAX + oix[r];
            float4 bx = g_pool_box[o];
            det[0] = bx.x; det[1] = bx.y; det[2] = bx.z; det[3] = bx.w;
            det[4] = osc[r];
            out[BB * DETS * 5 + b * DETS + r]             = (float)g_pool_lab[o];
            out[BB * DETS * 5 + BB * DETS + b * DETS + r] = 1.0f;
        } else {
            det[0] = det[1] = det[2] = det[3] = det[4] = 0.0f;
            out[BB * DETS * 5 + b * DETS + r]             = 1.0f;
            out[BB * DETS * 5 + BB * DETS + b * DETS + r] = 0.0f;
        }
    }

    // re-zero counters for the next launch (replaces reset_kernel)
    for (int i = tid; i < CC; i += blockDim.x) g_cand_cnt[b * CC + i] = 0;
    if (tid == 0) g_pool_cnt[b] = 0;
}

extern "C" void kernel_launch(void* const* d_in, const int* in_sizes, int n_in,
                              void* d_out, int out_size) {
    const float* logits = nullptr;  // 32*1000*105   = 3,360,000
    const float* reg    = nullptr;  // 32*1000*420   = 13,440,000
    const float* props  = nullptr;  // 32*1000*4     = 128,000
    for (int i = 0; i < n_in; i++) {
        if (in_sizes[i] == BB * NN * CC)       logits = (const float*)d_in[i];
        else if (in_sizes[i] == BB * NN * 4 * CC) reg  = (const float*)d_in[i];
        else if (in_sizes[i] == BB * NN * 4)   props  = (const float*)d_in[i];
    }
    float* out = (float*)d_out;

    score_decode_kernel<<<BB * NN / 8, 256>>>(logits, reg, props);
    nms_kernel<<<BB * (CC - 1), 128>>>();
    topk_kernel<<<BB, 256>>>(out);
}